// round 6
// baseline (speedup 1.0000x reference)
#include <cuda_runtime.h>
#include <cstdint>

// DWTModelFullBand: reference = idwt2(idwt2(dwt2(dwt2(x)))) == identity
// (verified R2, rel_err 6.2e-8). Kernel = D2D copy of 96 MiB.
//
// R5: PARTIAL L2 pinning. R4 pinned the whole 96MB input -> can't fit in
// 126MB L2 alongside streaming writes, no steady state. Now pin only the
// first 64MB (evict_last); stream the remaining 32MB of reads and ALL
// writes with evict_first so they never displace the pinned set.
// 64MB pinned + transient traffic < 126MB L2 -> stable residency possible.

struct __align__(32) f8 { uint32_t v[8]; };

__device__ __forceinline__ f8 ld_f8_evict_last(const f8* p) {
    f8 r;
    asm volatile(
        "ld.global.nc.L2::evict_last.v8.b32 {%0,%1,%2,%3,%4,%5,%6,%7}, [%8];"
        : "=r"(r.v[0]), "=r"(r.v[1]), "=r"(r.v[2]), "=r"(r.v[3]),
          "=r"(r.v[4]), "=r"(r.v[5]), "=r"(r.v[6]), "=r"(r.v[7])
        : "l"(p));
    return r;
}

__device__ __forceinline__ f8 ld_f8_evict_first(const f8* p) {
    f8 r;
    asm volatile(
        "ld.global.nc.L2::evict_first.v8.b32 {%0,%1,%2,%3,%4,%5,%6,%7}, [%8];"
        : "=r"(r.v[0]), "=r"(r.v[1]), "=r"(r.v[2]), "=r"(r.v[3]),
          "=r"(r.v[4]), "=r"(r.v[5]), "=r"(r.v[6]), "=r"(r.v[7])
        : "l"(p));
    return r;
}

__device__ __forceinline__ void st_f8_evict_first(f8* p, const f8& r) {
    asm volatile(
        "st.global.L2::evict_first.v8.b32 [%0], {%1,%2,%3,%4,%5,%6,%7,%8};"
        :: "l"(p),
           "r"(r.v[0]), "r"(r.v[1]), "r"(r.v[2]), "r"(r.v[3]),
           "r"(r.v[4]), "r"(r.v[5]), "r"(r.v[6]), "r"(r.v[7])
        : "memory");
}

__global__ __launch_bounds__(256)
void copy_f8_split_kernel(const f8* __restrict__ src,
                          f8* __restrict__ dst,
                          int n8, int n_pin) {
    int stride = gridDim.x * blockDim.x;
    int i = blockIdx.x * blockDim.x + threadIdx.x;
    #pragma unroll 4
    for (; i < n8; i += stride) {
        f8 r;
        if (i < n_pin) r = ld_f8_evict_last(src + i);   // pinned 64MB region
        else           r = ld_f8_evict_first(src + i);  // streaming 32MB tail
        st_f8_evict_first(dst + i, r);                  // streaming writes
    }
}

extern "C" void kernel_launch(void* const* d_in, const int* in_sizes, int n_in,
                              void* d_out, int out_size) {
    const f8* src = (const f8*)d_in[0];
    f8* dst = (f8*)d_out;
    int n8 = in_sizes[0] / 8;        // 3,145,728 chunks of 32B (96 MiB)
    int n_pin = (n8 / 3) * 2;        // pin first 2/3 = 64 MiB in L2

    int threads = 256;
    int blocks = 148 * 8;
    copy_f8_split_kernel<<<blocks, threads>>>(src, dst, n8, n_pin);
}

// round 8
// speedup vs baseline: 1.0182x; 1.0182x over previous
#include <cuda_runtime.h>
#include <cstdint>

// DWTModelFullBand: reference = idwt2(idwt2(dwt2(dwt2(x)))) == identity
// (verified R2, rel_err 6.2e-8). Kernel = D2D copy of 96 MiB.
//
// R6: burst-batched, tail-free copy. 3,145,728 x 32B chunks
//   = 4 outer iters x 4-chunk batch x 196,608 threads (768 blocks x 256)
// -> no bounds checks, no tail wave. Each iteration issues 4 independent
// 32B loads (read burst), then 4 stores (write burst): coarser DRAM
// read/write grouping, fewer bus turnarounds. Keep R4's hint scheme
// (evict_last loads / evict_first stores) which was the best measured.

struct __align__(32) f8 { uint32_t v[8]; };

__device__ __forceinline__ f8 ld_f8_el(const f8* p) {
    f8 r;
    asm volatile(
        "ld.global.nc.L2::evict_last.v8.b32 {%0,%1,%2,%3,%4,%5,%6,%7}, [%8];"
        : "=r"(r.v[0]), "=r"(r.v[1]), "=r"(r.v[2]), "=r"(r.v[3]),
          "=r"(r.v[4]), "=r"(r.v[5]), "=r"(r.v[6]), "=r"(r.v[7])
        : "l"(p));
    return r;
}

__device__ __forceinline__ void st_f8_ef(f8* p, const f8& r) {
    asm volatile(
        "st.global.L2::evict_first.v8.b32 [%0], {%1,%2,%3,%4,%5,%6,%7,%8};"
        :: "l"(p),
           "r"(r.v[0]), "r"(r.v[1]), "r"(r.v[2]), "r"(r.v[3]),
           "r"(r.v[4]), "r"(r.v[5]), "r"(r.v[6]), "r"(r.v[7])
        : "memory");
}

static constexpr int BLOCKS  = 768;
static constexpr int THREADS = 256;
static constexpr int T       = BLOCKS * THREADS;   // 196,608
static constexpr int N8      = 3145728;            // 25,165,824 floats / 8
static_assert(N8 == 16 * T, "tail-free layout requires N8 == 16*T");

__global__ __launch_bounds__(THREADS)
void copy_f8_batched_kernel(const f8* __restrict__ src,
                            f8* __restrict__ dst) {
    int tid = blockIdx.x * THREADS + threadIdx.x;
    #pragma unroll
    for (int it = 0; it < 4; it++) {
        int base = it * (4 * T) + tid;
        // read burst: 4 independent 32B loads
        f8 r0 = ld_f8_el(src + base);
        f8 r1 = ld_f8_el(src + base + T);
        f8 r2 = ld_f8_el(src + base + 2 * T);
        f8 r3 = ld_f8_el(src + base + 3 * T);
        // write burst
        st_f8_ef(dst + base,         r0);
        st_f8_ef(dst + base + T,     r1);
        st_f8_ef(dst + base + 2 * T, r2);
        st_f8_ef(dst + base + 3 * T, r3);
    }
}

// Generic fallback (any size) — kept for safety if shapes ever differ.
__global__ __launch_bounds__(THREADS)
void copy_f8_generic_kernel(const f8* __restrict__ src,
                            f8* __restrict__ dst, int n8) {
    int stride = gridDim.x * blockDim.x;
    for (int i = blockIdx.x * blockDim.x + threadIdx.x; i < n8; i += stride)
        st_f8_ef(dst + i, ld_f8_el(src + i));
}

extern "C" void kernel_launch(void* const* d_in, const int* in_sizes, int n_in,
                              void* d_out, int out_size) {
    const f8* src = (const f8*)d_in[0];
    f8* dst = (f8*)d_out;
    int n8 = in_sizes[0] / 8;

    if (n8 == N8) {
        copy_f8_batched_kernel<<<BLOCKS, THREADS>>>(src, dst);
    } else {
        copy_f8_generic_kernel<<<1184, THREADS>>>(src, dst, n8);
    }
}

// round 9
// speedup vs baseline: 1.0652x; 1.0462x over previous
#include <cuda_runtime.h>
#include <cstdint>

// DWTModelFullBand: reference = idwt2(idwt2(dwt2(dwt2(x)))) == identity
// (verified R2, rel_err 6.2e-8). Required work = D2D copy of 96 MiB.
//
// R8: route the copy through the COPY ENGINE instead of SMs.
// cudaMemcpyAsync D2D is explicitly graph-capturable per harness rules and
// becomes a memcpy node in the captured graph. Device-side bandwidth ceiling
// is path-independent (~7 TB/s mixed R/W, measured R4-R6), so this probes
// the per-replay node overhead (constant ~9.3us gap between dur_us and
// kernel time on the SM path) and CE read/write burst scheduling.

extern "C" void kernel_launch(void* const* d_in, const int* in_sizes, int n_in,
                              void* d_out, int out_size) {
    size_t bytes = (size_t)in_sizes[0] * sizeof(float);  // 96 MiB
    cudaMemcpyAsync(d_out, d_in[0], bytes, cudaMemcpyDeviceToDevice, 0);
}